// round 10
// baseline (speedup 1.0000x reference)
#include <cuda_runtime.h>
#include <cuda_bf16.h>
#include <cstdint>

#define D_VEC 8             // 32 floats = 8 float4 per node row
#define GROUPS_PER_CTA 32   // 256 threads / 8 lanes per group

__global__ void zero_out_kernel(float4* __restrict__ out, int n4) {
    int i = blockIdx.x * blockDim.x + threadIdx.x;
    if (i < n4) out[i] = make_float4(0.f, 0.f, 0.f, 0.f);
}

__device__ __forceinline__ uint32_t smem_u32(const void* p) {
    return (uint32_t)__cvta_generic_to_shared(p);
}

__device__ __forceinline__ void red_one(float4* __restrict__ out,
                                        int target, int j,
                                        float4 v, float w) {
    float4 r;
    r.x = v.x * w;
    r.y = v.y * w;
    r.z = v.z * w;
    r.w = v.w * w;
    asm volatile("red.global.add.v4.f32 [%0], {%1, %2, %3, %4};"
                 :: "l"(out + target * D_VEC + j),
                    "f"(r.x), "f"(r.y), "f"(r.z), "f"(r.w)
                 : "memory");
}

// Hybrid scatter: first `blocks_red` CTAs push their edges through the
// L1tex RED pipe; remaining CTAs push theirs through SMEM + TMA bulk
// reduce (shared port + TMA engine). If the two paths are limited by
// different SM pipes, they overlap; if the LTS atomic ALU is the shared
// floor, this is neutral and tells us so.
__global__ void __launch_bounds__(256)
graphconv_hybrid_kernel(const float4* __restrict__ input,
                        const int4*   __restrict__ sidx4,
                        const int4*   __restrict__ tidx4,
                        const float4* __restrict__ enorm4,
                        const float4* __restrict__ esgn4,
                        float4* __restrict__ out,
                        int red_quads, int blocks_red, int tma_quads) {
    // Staging for the TMA path: 4 slots of 128B per 8-lane group (16KB).
    __shared__ __align__(128) float4 stage[GROUPS_PER_CTA][4][D_VEC];

    int tid = threadIdx.x;
    int j = tid & 7;               // float4 slot within the 128B row
    int lane = tid & 31;

    if ((int)blockIdx.x < blocks_red) {
        // ---------------- RED path (L1tex) ----------------
        int gid = blockIdx.x * 256 + tid;
        int q = gid >> 3;
        if (q >= red_quads) return;

        int4   s  = __ldg(sidx4  + q);
        int4   t  = __ldg(tidx4  + q);
        float4 en = __ldg(enorm4 + q);
        float4 eg = __ldg(esgn4  + q);

        float4 v0 = __ldg(input + s.x * D_VEC + j);
        float4 v1 = __ldg(input + s.y * D_VEC + j);
        float4 v2 = __ldg(input + s.z * D_VEC + j);
        float4 v3 = __ldg(input + s.w * D_VEC + j);

        red_one(out, t.x, j, v0, en.x * eg.x);
        red_one(out, t.y, j, v1, en.y * eg.y);
        red_one(out, t.z, j, v2, en.z * eg.z);
        red_one(out, t.w, j, v3, en.w * eg.w);
    } else {
        // ---------------- TMA bulk-reduce path ----------------
        int gid = ((int)blockIdx.x - blocks_red) * 256 + tid;
        int q0 = gid >> 3;
        if (q0 >= tma_quads) return;
        int q = red_quads + q0;

        int grp = tid >> 3;
        unsigned gmask = 0xFFu << (lane & 24);
        bool leader = (j == 0);

        int4   s  = __ldg(sidx4  + q);
        int4   t  = __ldg(tidx4  + q);
        float4 en = __ldg(enorm4 + q);
        float4 eg = __ldg(esgn4  + q);

        int   ss[4] = {s.x, s.y, s.z, s.w};
        int   tt[4] = {t.x, t.y, t.z, t.w};
        float ww[4] = {en.x * eg.x, en.y * eg.y, en.z * eg.z, en.w * eg.w};

        float4 v[4];
#pragma unroll
        for (int i = 0; i < 4; i++)
            v[i] = __ldg(input + ss[i] * D_VEC + j);

        // Stage all 4 scaled rows, then one sync + one fence + 4 cp.
#pragma unroll
        for (int i = 0; i < 4; i++) {
            float4 r;
            r.x = v[i].x * ww[i]; r.y = v[i].y * ww[i];
            r.z = v[i].z * ww[i]; r.w = v[i].w * ww[i];
            stage[grp][i][j] = r;
        }
        __syncwarp(gmask);

        if (leader) {
            asm volatile("fence.proxy.async.shared::cta;" ::: "memory");
#pragma unroll
            for (int i = 0; i < 4; i++) {
                asm volatile(
                    "cp.reduce.async.bulk.global.shared::cta.bulk_group.add.f32 "
                    "[%0], [%1], 128;"
                    :: "l"(out + tt[i] * D_VEC),
                       "r"(smem_u32(&stage[grp][i][0]))
                    : "memory");
            }
            asm volatile("cp.async.bulk.commit_group;" ::: "memory");
            // SMEM must stay alive until the TMA engine has read it.
            asm volatile("cp.async.bulk.wait_group.read 0;" ::: "memory");
        }
    }
}

extern "C" void kernel_launch(void* const* d_in, const int* in_sizes, int n_in,
                              void* d_out, int out_size) {
    const float4* input = (const float4*)d_in[0];   // [n_nodes, 32] fp32
    const int*    eidx  = (const int*)d_in[1];      // [2, n_edges] int32
    const float*  enorm = (const float*)d_in[2];    // [n_edges]
    const float*  esgn  = (const float*)d_in[3];    // [n_edges]
    float4*       out   = (float4*)d_out;           // [n_nodes, 32] fp32

    int n_edges = in_sizes[2];
    const int* sidx = eidx;
    const int* tidx = eidx + n_edges;

    // Zero the output (harness poisons it to 0xAA).
    int n4 = out_size / 4;
    zero_out_kernel<<<(n4 + 255) / 256, 256>>>(out, n4);

    int n_quads   = n_edges >> 2;          // n_edges divisible by 4
    int red_quads = n_quads / 2;           // 50/50 split between paths
    int tma_quads = n_quads - red_quads;

    int blocks_red = (red_quads + 31) / 32;   // 32 quads per 256-thread CTA
    int blocks_tma = (tma_quads + 31) / 32;

    graphconv_hybrid_kernel<<<blocks_red + blocks_tma, 256>>>(
        input, (const int4*)sidx, (const int4*)tidx,
        (const float4*)enorm, (const float4*)esgn,
        (float4*)out, red_quads, blocks_red, tma_quads);
}